// round 2
// baseline (speedup 1.0000x reference)
#include <cuda_runtime.h>
#include <math.h>

#define NN   10000
#define DIN  128
#define DHID 128
#define DOUT 64

// ---------------- scratch (device globals; no allocation allowed) ----------
__device__ float  g_agg0[NN * DIN];
__device__ float  g_h0  [NN * DHID];
__device__ float  g_agg1[NN * DHID];
__device__ float  g_h1  [NN * DOUT];
__device__ float  g_hn  [NN * DOUT];
__device__ double g_loss[2];
__device__ int    g_is64;

// ---------------- zero scratch ---------------------------------------------
__global__ void zero_kernel() {
    int i = blockIdx.x * blockDim.x + threadIdx.x;
    if (i < NN * DIN)  g_agg0[i] = 0.f;
    if (i < NN * DHID) g_agg1[i] = 0.f;
    if (i < 2)         g_loss[i] = 0.0;
}

// ---------------- detect edge-index dtype (int64 vs int32) -----------------
__global__ void detect_kernel(const void* __restrict__ ei, int E, int n) {
    if (blockIdx.x == 0 && threadIdx.x == 0) {
        const long long* p = (const long long*)ei;
        int m = E < 1024 ? E : 1024;
        int is64 = 1;
        for (int i = 0; i < m; i++) {
            long long v = p[i];
            if (v < 0 || v >= (long long)n) { is64 = 0; break; }
        }
        g_is64 = is64;
    }
}

__device__ __forceinline__ long long load_idx(const void* p, long long i, int is64) {
    return is64 ? ((const long long*)p)[i] : (long long)((const int*)p)[i];
}

// vector reduction: one REDG.128 instead of 4 REDG.32
__device__ __forceinline__ void red_add_v4(float* addr, float4 v) {
    asm volatile("red.global.add.v4.f32 [%0], {%1, %2, %3, %4};"
                 :: "l"(addr), "f"(v.x), "f"(v.y), "f"(v.z), "f"(v.w)
                 : "memory");
}

// ---------------- scatter-add: agg[dst] += feat[src] (D=128) ---------------
// phase 0: feat = x (param), out = g_agg0 ; phase 1: feat = g_h0, out = g_agg1
__global__ void scatter_kernel(const float* __restrict__ xin,
                               const void* __restrict__ ei, int E, int phase) {
    long long idx = (long long)blockIdx.x * blockDim.x + threadIdx.x;
    long long total = (long long)E * (DIN / 4);
    if (idx >= total) return;
    int e = (int)(idx >> 5);       // DIN/4 = 32 chunks per edge
    int c = ((int)idx & 31) * 4;
    int is64 = g_is64;
    long long s = load_idx(ei, e, is64);
    long long d = load_idx(ei, (long long)E + e, is64);
    const float* feat = (phase == 0) ? xin : g_h0;
    float* out = (phase == 0) ? g_agg0 : g_agg1;
    float4 v = *(const float4*)(feat + s * DIN + c);
    red_add_v4(out + d * DIN + c, v);
}

// ---------------- dense layer 0: h0 = tanh(agg0@Wrel + x@Wroot + b) --------
__global__ void dense0_kernel(const float* __restrict__ x,
                              const float* __restrict__ Wrel,
                              const float* __restrict__ Wroot,
                              const float* __restrict__ b) {
    int row = blockIdx.x;
    int t = threadIdx.x;   // 128 threads, one output column each
    __shared__ float xs[DIN];
    __shared__ float as[DIN];
    xs[t] = x[(long long)row * DIN + t];
    as[t] = g_agg0[(long long)row * DIN + t];
    __syncthreads();
    float acc = b[t];
#pragma unroll 16
    for (int k = 0; k < DIN; k++) {
        acc = fmaf(xs[k], Wroot[k * DHID + t], acc);
        acc = fmaf(as[k], Wrel [k * DHID + t], acc);
    }
    g_h0[(long long)row * DHID + t] = tanhf(acc);
}

// ---------------- dense layer 1 + row normalization ------------------------
__global__ void dense1_kernel(const float* __restrict__ Wrel,
                              const float* __restrict__ Wroot,
                              const float* __restrict__ b) {
    int row = blockIdx.x;
    int t = threadIdx.x;   // 64 threads
    __shared__ float hs[DHID];
    __shared__ float as[DHID];
    __shared__ float wsum[2];
    hs[t]      = g_h0[(long long)row * DHID + t];
    hs[t + 64] = g_h0[(long long)row * DHID + t + 64];
    as[t]      = g_agg1[(long long)row * DHID + t];
    as[t + 64] = g_agg1[(long long)row * DHID + t + 64];
    __syncthreads();
    float acc = b[t];
#pragma unroll 16
    for (int k = 0; k < DHID; k++) {
        acc = fmaf(hs[k], Wroot[k * DOUT + t], acc);
        acc = fmaf(as[k], Wrel [k * DOUT + t], acc);
    }
    g_h1[(long long)row * DOUT + t] = acc;
    float sq = acc * acc;
#pragma unroll
    for (int off = 16; off; off >>= 1) sq += __shfl_xor_sync(0xffffffffu, sq, off);
    if ((t & 31) == 0) wsum[t >> 5] = sq;
    __syncthreads();
    float nrm = sqrtf(wsum[0] + wsum[1]);
    g_hn[(long long)row * DOUT + t] = acc / fmaxf(nrm, 1e-8f);
}

// ---------------- reconstruction loss (warp per edge, double accum) --------
__global__ void loss_kernel(const void* __restrict__ ei,
                            const void* __restrict__ nei, int E) {
    __shared__ double sh[2];
    if (threadIdx.x < 2) sh[threadIdx.x] = 0.0;
    __syncthreads();
    int is64 = g_is64;
    int wglobal = (blockIdx.x * blockDim.x + threadIdx.x) >> 5;
    int lane = threadIdx.x & 31;
    int nwarps = (gridDim.x * blockDim.x) >> 5;
    double pos = 0.0, neg = 0.0;
    for (int task = wglobal; task < 2 * E; task += nwarps) {
        int is_neg = task >= E;
        int e = is_neg ? task - E : task;
        const void* idx = is_neg ? nei : ei;
        long long s = load_idx(idx, e, is64);
        long long d = load_idx(idx, (long long)E + e, is64);
        const float* a = g_h1 + s * DOUT;
        const float* bp = g_h1 + d * DOUT;
        float p = a[lane] * bp[lane] + a[lane + 32] * bp[lane + 32];
#pragma unroll
        for (int off = 16; off; off >>= 1) p += __shfl_xor_sync(0xffffffffu, p, off);
        if (lane == 0) {
            float z = is_neg ? p : -p;   // softplus argument
            float sp = fmaxf(z, 0.f) + log1pf(expf(-fabsf(z)));
            if (is_neg) neg += (double)sp; else pos += (double)sp;
        }
    }
    if (lane == 0) {
        atomicAdd(&sh[0], pos);
        atomicAdd(&sh[1], neg);
    }
    __syncthreads();
    if (threadIdx.x == 0) {
        atomicAdd(&g_loss[0], sh[0]);
        atomicAdd(&g_loss[1], sh[1]);
    }
}

// ---------------- sim matrix: sigmoid(hn @ hn^T), 128x128 tiles ------------
__global__ void __launch_bounds__(256) sim_kernel(float* __restrict__ out, int n) {
    __shared__ float As[32][132];   // k-major, padded for 16B-aligned float4
    __shared__ float Bs[32][132];
    int bi = blockIdx.y, bj = blockIdx.x;
    int tid = threadIdx.x;
    int tx = tid & 15, ty = tid >> 4;
    int row0 = bi * 128, col0 = bj * 128;

    float acc[8][8];
#pragma unroll
    for (int i = 0; i < 8; i++)
#pragma unroll
        for (int j = 0; j < 8; j++) acc[i][j] = 0.f;

    for (int kt = 0; kt < DOUT; kt += 32) {
#pragma unroll
        for (int l = 0; l < 4; l++) {
            int f = tid + l * 256;        // 0..1023
            int r = f >> 3;               // 0..127
            int kc = (f & 7) * 4;         // 0..28
            int gr = row0 + r;
            int gc = col0 + r;
            float4 va = make_float4(0.f, 0.f, 0.f, 0.f);
            float4 vb = make_float4(0.f, 0.f, 0.f, 0.f);
            if (gr < n) va = *(const float4*)(g_hn + (long long)gr * DOUT + kt + kc);
            if (gc < n) vb = *(const float4*)(g_hn + (long long)gc * DOUT + kt + kc);
            As[kc + 0][r] = va.x; As[kc + 1][r] = va.y;
            As[kc + 2][r] = va.z; As[kc + 3][r] = va.w;
            Bs[kc + 0][r] = vb.x; Bs[kc + 1][r] = vb.y;
            Bs[kc + 2][r] = vb.z; Bs[kc + 3][r] = vb.w;
        }
        __syncthreads();
#pragma unroll
        for (int k = 0; k < 32; k++) {
            float a[8], b[8];
            *(float4*)&a[0] = *(const float4*)&As[k][ty * 4];
            *(float4*)&a[4] = *(const float4*)&As[k][64 + ty * 4];
            *(float4*)&b[0] = *(const float4*)&Bs[k][tx * 4];
            *(float4*)&b[4] = *(const float4*)&Bs[k][64 + tx * 4];
#pragma unroll
            for (int i = 0; i < 8; i++)
#pragma unroll
                for (int j = 0; j < 8; j++)
                    acc[i][j] = fmaf(a[i], b[j], acc[i][j]);
        }
        __syncthreads();
    }

#pragma unroll
    for (int i = 0; i < 8; i++) {
        int r = row0 + ((i < 4) ? (ty * 4 + i) : (64 + ty * 4 + i - 4));
        if (r >= n) continue;
        long long base = (long long)r * n;
#pragma unroll
        for (int jg = 0; jg < 2; jg++) {
            int c0 = col0 + jg * 64 + tx * 4;
            float4 v;
            v.x = 1.f / (1.f + __expf(-acc[i][jg * 4 + 0]));
            v.y = 1.f / (1.f + __expf(-acc[i][jg * 4 + 1]));
            v.z = 1.f / (1.f + __expf(-acc[i][jg * 4 + 2]));
            v.w = 1.f / (1.f + __expf(-acc[i][jg * 4 + 3]));
            if (c0 + 3 < n) {
                *(float4*)(out + base + c0) = v;
            } else {
                if (c0 + 0 < n) out[base + c0 + 0] = v.x;
                if (c0 + 1 < n) out[base + c0 + 1] = v.y;
                if (c0 + 2 < n) out[base + c0 + 2] = v.z;
                if (c0 + 3 < n) out[base + c0 + 3] = v.w;
            }
        }
    }
}

// ---------------- final scalar ---------------------------------------------
__global__ void finalize_kernel(float* __restrict__ out, int E, long long loss_off,
                                int has_loss) {
    if (has_loss && threadIdx.x == 0 && blockIdx.x == 0) {
        out[loss_off] = (float)(g_loss[0] / (double)E + g_loss[1] / (double)E);
    }
}

// ---------------- launcher -------------------------------------------------
extern "C" void kernel_launch(void* const* d_in, const int* in_sizes, int n_in,
                              void* d_out, int out_size) {
    // inputs: 0=q, 1=x, 2=edge_index, 3=neg_edge_index,
    //         4=W_rel0, 5=W_root0, 6=b0, 7=W_rel1, 8=W_root1, 9=b1
    const float* x      = (const float*)d_in[1];
    const void*  ei     = d_in[2];
    const void*  nei    = d_in[3];
    const float* Wrel0  = (const float*)d_in[4];
    const float* Wroot0 = (const float*)d_in[5];
    const float* b0     = (const float*)d_in[6];
    const float* Wrel1  = (const float*)d_in[7];
    const float* Wroot1 = (const float*)d_in[8];
    const float* b1     = (const float*)d_in[9];

    int n = in_sizes[1] / DIN;      // 10000
    int E = in_sizes[2] / 2;        // 320000
    float* out = (float*)d_out;

    zero_kernel<<<(NN * DIN + 255) / 256, 256>>>();
    detect_kernel<<<1, 32>>>(ei, E, n);

    long long sc_total = (long long)E * 32;
    unsigned sc_blocks = (unsigned)((sc_total + 255) / 256);
    scatter_kernel<<<sc_blocks, 256>>>(x, ei, E, 0);
    dense0_kernel<<<n, 128>>>(x, Wrel0, Wroot0, b0);
    scatter_kernel<<<sc_blocks, 256>>>(x, ei, E, 1);
    dense1_kernel<<<n, 64>>>(Wrel1, Wroot1, b1);
    loss_kernel<<<1024, 256>>>(ei, nei, E);

    dim3 grid((n + 127) / 128, (n + 127) / 128);
    sim_kernel<<<grid, 256>>>(out, n);

    long long nn2 = (long long)n * n;
    int has_loss = ((long long)out_size > nn2) ? 1 : 0;
    finalize_kernel<<<1, 1>>>(out, E, nn2, has_loss);
}

// round 12
// speedup vs baseline: 1.3502x; 1.3502x over previous
#include <cuda_runtime.h>
#include <math.h>

#define NN    10000
#define DIN   128
#define DHID  128
#define DOUT  64
#define EMAX  524288

// ---------------- scratch (device globals; no allocation allowed) ----------
__device__ float  g_agg0[NN * DIN];
__device__ float  g_h0  [NN * DHID];
__device__ float  g_agg1[NN * DHID];
__device__ float  g_h1  [NN * DOUT];
__device__ float  g_hn  [NN * DOUT];
__device__ double g_loss[2];
__device__ int    g_is64;
__device__ int    g_deg [NN];
__device__ int    g_off [NN];
__device__ int    g_cur [NN];
__device__ int    g_srclist[EMAX];

// ---------------- zero scratch ---------------------------------------------
__global__ void zero_kernel() {
    int i = blockIdx.x * blockDim.x + threadIdx.x;
    if (i < NN) g_deg[i] = 0;
    if (i < 2)  g_loss[i] = 0.0;
}

// ---------------- detect edge-index dtype (int64 vs int32) -----------------
__global__ void detect_kernel(const void* __restrict__ ei, int E, int n) {
    if (blockIdx.x == 0 && threadIdx.x == 0) {
        const long long* p = (const long long*)ei;
        int m = E < 1024 ? E : 1024;
        int is64 = 1;
        for (int i = 0; i < m; i++) {
            long long v = p[i];
            if (v < 0 || v >= (long long)n) { is64 = 0; break; }
        }
        g_is64 = is64;
    }
}

__device__ __forceinline__ long long load_idx(const void* p, long long i, int is64) {
    return is64 ? ((const long long*)p)[i] : (long long)((const int*)p)[i];
}

// ---------------- CSR build: count, scan, fill -----------------------------
__global__ void count_kernel(const void* __restrict__ ei, int E) {
    int e = blockIdx.x * blockDim.x + threadIdx.x;
    if (e >= E) return;
    int is64 = g_is64;
    int d = (int)load_idx(ei, (long long)E + e, is64);
    atomicAdd(&g_deg[d], 1);
}

__global__ void scan_kernel(int n) {
    __shared__ int ps[1024];
    int t = threadIdx.x;
    int chunk = (n + 1023) >> 10;
    int start = t * chunk;
    int end = start + chunk; if (end > n) end = n;
    int local = 0;
    for (int i = start; i < end && i < n; i++) local += g_deg[i];
    ps[t] = local;
    __syncthreads();
    for (int off = 1; off < 1024; off <<= 1) {
        int v = (t >= off) ? ps[t - off] : 0;
        __syncthreads();
        ps[t] += v;
        __syncthreads();
    }
    int running = (t == 0) ? 0 : ps[t - 1];
    for (int i = start; i < end && i < n; i++) {
        g_off[i] = running;
        g_cur[i] = running;
        running += g_deg[i];
    }
}

__global__ void fill_kernel(const void* __restrict__ ei, int E) {
    int e = blockIdx.x * blockDim.x + threadIdx.x;
    if (e >= E) return;
    int is64 = g_is64;
    int s = (int)load_idx(ei, e, is64);
    int d = (int)load_idx(ei, (long long)E + e, is64);
    int pos = atomicAdd(&g_cur[d], 1);
    g_srclist[pos] = s;
}

// ---------------- gather aggregation: agg[n] = sum feat[src] ----------------
__global__ void gather_kernel(const float* __restrict__ feat,
                              float* __restrict__ outp) {
    int nidx = blockIdx.x;
    int t = threadIdx.x;  // 128
    int off = g_off[nidx];
    int deg = g_deg[nidx];
    float acc = 0.f;
    int i = 0;
    for (; i + 4 <= deg; i += 4) {
        int s0 = g_srclist[off + i + 0];
        int s1 = g_srclist[off + i + 1];
        int s2 = g_srclist[off + i + 2];
        int s3 = g_srclist[off + i + 3];
        float v0 = feat[(size_t)s0 * 128 + t];
        float v1 = feat[(size_t)s1 * 128 + t];
        float v2 = feat[(size_t)s2 * 128 + t];
        float v3 = feat[(size_t)s3 * 128 + t];
        acc += (v0 + v1) + (v2 + v3);
    }
    for (; i < deg; i++) {
        int s = g_srclist[off + i];
        acc += feat[(size_t)s * 128 + t];
    }
    outp[(size_t)nidx * 128 + t] = acc;
}

// ---------------- dense layer 0: 8 rows/block, h0 = tanh(...) --------------
__global__ void __launch_bounds__(128) dense0_kernel(
        const float* __restrict__ x, const float* __restrict__ Wrel,
        const float* __restrict__ Wroot, const float* __restrict__ b, int n) {
    int rowb = blockIdx.x * 8;
    int t = threadIdx.x;  // 128
    __shared__ float xs[8][128];
    __shared__ float as[8][128];
#pragma unroll
    for (int r = 0; r < 8; r++) {
        int rr = rowb + r;
        float xv = 0.f, av = 0.f;
        if (rr < n) {
            xv = x[(size_t)rr * DIN + t];
            av = g_agg0[(size_t)rr * DIN + t];
        }
        xs[r][t] = xv;
        as[r][t] = av;
    }
    __syncthreads();
    float acc[8];
    float bb = b[t];
#pragma unroll
    for (int r = 0; r < 8; r++) acc[r] = bb;
#pragma unroll 4
    for (int k = 0; k < DIN; k++) {
        float wr = Wroot[k * DHID + t];
        float wl = Wrel [k * DHID + t];
#pragma unroll
        for (int r = 0; r < 8; r++) {
            acc[r] = fmaf(xs[r][k], wr, acc[r]);
            acc[r] = fmaf(as[r][k], wl, acc[r]);
        }
    }
#pragma unroll
    for (int r = 0; r < 8; r++) {
        int rr = rowb + r;
        if (rr < n) g_h0[(size_t)rr * DHID + t] = tanhf(acc[r]);
    }
}

// ---------------- dense layer 1 + row normalization (8 rows/block) ---------
__global__ void __launch_bounds__(64) dense1_kernel(
        const float* __restrict__ Wrel, const float* __restrict__ Wroot,
        const float* __restrict__ b, int n) {
    int rowb = blockIdx.x * 8;
    int t = threadIdx.x;  // 64
    __shared__ float hs[8][128];
    __shared__ float as[8][128];
    __shared__ float wsum[8][2];
#pragma unroll
    for (int r = 0; r < 8; r++) {
        int rr = rowb + r;
        float h0v = 0.f, h1v = 0.f, a0v = 0.f, a1v = 0.f;
        if (rr < n) {
            h0v = g_h0  [(size_t)rr * DHID + t];
            h1v = g_h0  [(size_t)rr * DHID + t + 64];
            a0v = g_agg1[(size_t)rr * DHID + t];
            a1v = g_agg1[(size_t)rr * DHID + t + 64];
        }
        hs[r][t] = h0v; hs[r][t + 64] = h1v;
        as[r][t] = a0v; as[r][t + 64] = a1v;
    }
    __syncthreads();
    float acc[8];
    float bb = b[t];
#pragma unroll
    for (int r = 0; r < 8; r++) acc[r] = bb;
#pragma unroll 4
    for (int k = 0; k < DHID; k++) {
        float wr = Wroot[k * DOUT + t];
        float wl = Wrel [k * DOUT + t];
#pragma unroll
        for (int r = 0; r < 8; r++) {
            acc[r] = fmaf(hs[r][k], wr, acc[r]);
            acc[r] = fmaf(as[r][k], wl, acc[r]);
        }
    }
    int lane = t & 31, wid = t >> 5;
#pragma unroll
    for (int r = 0; r < 8; r++) {
        float sq = acc[r] * acc[r];
#pragma unroll
        for (int off = 16; off; off >>= 1) sq += __shfl_xor_sync(0xffffffffu, sq, off);
        if (lane == 0) wsum[r][wid] = sq;
    }
    __syncthreads();
#pragma unroll
    for (int r = 0; r < 8; r++) {
        int rr = rowb + r;
        if (rr >= n) continue;
        float nrm = sqrtf(wsum[r][0] + wsum[r][1]);
        g_h1[(size_t)rr * DOUT + t] = acc[r];
        g_hn[(size_t)rr * DOUT + t] = acc[r] / fmaxf(nrm, 1e-8f);
    }
}

// ---------------- reconstruction loss (warp per edge, double accum) --------
__global__ void loss_kernel(const void* __restrict__ ei,
                            const void* __restrict__ nei, int E) {
    __shared__ double sh[2];
    if (threadIdx.x < 2) sh[threadIdx.x] = 0.0;
    __syncthreads();
    int is64 = g_is64;
    int wglobal = (blockIdx.x * blockDim.x + threadIdx.x) >> 5;
    int lane = threadIdx.x & 31;
    int nwarps = (gridDim.x * blockDim.x) >> 5;
    double pos = 0.0, neg = 0.0;
    for (int task = wglobal; task < 2 * E; task += nwarps) {
        int is_neg = task >= E;
        int e = is_neg ? task - E : task;
        const void* idx = is_neg ? nei : ei;
        long long s = load_idx(idx, e, is64);
        long long d = load_idx(idx, (long long)E + e, is64);
        const float* a = g_h1 + s * DOUT;
        const float* bp = g_h1 + d * DOUT;
        float p = a[lane] * bp[lane] + a[lane + 32] * bp[lane + 32];
#pragma unroll
        for (int off = 16; off; off >>= 1) p += __shfl_xor_sync(0xffffffffu, p, off);
        if (lane == 0) {
            float z = is_neg ? p : -p;   // softplus argument
            float sp = fmaxf(z, 0.f) + log1pf(expf(-fabsf(z)));
            if (is_neg) neg += (double)sp; else pos += (double)sp;
        }
    }
    if (lane == 0) {
        atomicAdd(&sh[0], pos);
        atomicAdd(&sh[1], neg);
    }
    __syncthreads();
    if (threadIdx.x == 0) {
        atomicAdd(&g_loss[0], sh[0]);
        atomicAdd(&g_loss[1], sh[1]);
    }
}

// ---------------- sim matrix via tf32 mma.sync -----------------------------
__device__ __forceinline__ unsigned f2tf32(float f) {
    unsigned u;
    asm("cvt.rna.tf32.f32 %0, %1;" : "=r"(u) : "f"(f));
    return u;
}

// 128x128 tile per block, 256 threads = 8 warps (4x2), warp tile 32x64.
// K = 64 loaded whole into smem. Swizzled layout: addr = row*64 + (k ^ ((row&7)<<2))
__global__ void __launch_bounds__(256) sim_mma_kernel(float* __restrict__ out, int n) {
    extern __shared__ unsigned sm[];
    unsigned* As = sm;               // 128*64
    unsigned* Bs = sm + 128 * 64;    // 128*64
    int tid = threadIdx.x;
    int row0 = blockIdx.y * 128, col0 = blockIdx.x * 128;

#pragma unroll
    for (int l = 0; l < 8; l++) {
        int f = tid + l * 256;        // 0..2047
        int r = f >> 4;               // 0..127
        int kc = (f & 15) * 4;        // 0..60
        int ra = row0 + r, rb = col0 + r;
        float4 va = make_float4(0.f, 0.f, 0.f, 0.f);
        float4 vb = make_float4(0.f, 0.f, 0.f, 0.f);
        if (ra < n) va = *(const float4*)(g_hn + (size_t)ra * DOUT + kc);
        if (rb < n) vb = *(const float4*)(g_hn + (size_t)rb * DOUT + kc);
        int sc = kc ^ ((r & 7) << 2);
        uint4 ua = make_uint4(f2tf32(va.x), f2tf32(va.y), f2tf32(va.z), f2tf32(va.w));
        uint4 ub = make_uint4(f2tf32(vb.x), f2tf32(vb.y), f2tf32(vb.z), f2tf32(vb.w));
        *(uint4*)(As + r * 64 + sc) = ua;
        *(uint4*)(Bs + r * 64 + sc) = ub;
    }
    __syncthreads();

    int w = tid >> 5, lane = tid & 31;
    int wm = w & 3, wn = w >> 2;      // warp at rows wm*32, cols wn*64
    int g = lane >> 2, t4 = lane & 3;

    float c[2][8][4];
#pragma unroll
    for (int mt = 0; mt < 2; mt++)
#pragma unroll
        for (int nt = 0; nt < 8; nt++)
#pragma unroll
            for (int q = 0; q < 4; q++) c[mt][nt][q] = 0.f;

#pragma unroll
    for (int ks = 0; ks < 8; ks++) {
        int k0 = ks * 8;
        unsigned a[2][4];
#pragma unroll
        for (int mt = 0; mt < 2; mt++) {
            int r0 = wm * 32 + mt * 16 + g;
            int r1 = r0 + 8;
            int sw0 = (r0 & 7) << 2;
            int sw1 = (r1 & 7) << 2;
            a[mt][0] = As[r0 * 64 + ((k0 + t4) ^ sw0)];
            a[mt][1] = As[r1 * 64 + ((k0 + t4) ^ sw1)];
            a[mt][2] = As[r0 * 64 + ((k0 + t4 + 4) ^ sw0)];
            a[mt][3] = As[r1 * 64 + ((k0 + t4 + 4) ^ sw1)];
        }
#pragma unroll
        for (int nt = 0; nt < 8; nt++) {
            int cb = wn * 64 + nt * 8 + g;
            int swb = (cb & 7) << 2;
            unsigned b0 = Bs[cb * 64 + ((k0 + t4) ^ swb)];
            unsigned b1 = Bs[cb * 64 + ((k0 + t4 + 4) ^ swb)];
#pragma unroll
            for (int mt = 0; mt < 2; mt++) {
                asm volatile(
                    "mma.sync.aligned.m16n8k8.row.col.f32.tf32.tf32.f32 "
                    "{%0,%1,%2,%3}, {%4,%5,%6,%7}, {%8,%9}, {%0,%1,%2,%3};"
                    : "+f"(c[mt][nt][0]), "+f"(c[mt][nt][1]),
                      "+f"(c[mt][nt][2]), "+f"(c[mt][nt][3])
                    : "r"(a[mt][0]), "r"(a[mt][1]), "r"(a[mt][2]), "r"(a[mt][3]),
                      "r"(b0), "r"(b1));
            }
        }
    }

    // epilogue: sigmoid + store
#pragma unroll
    for (int mt = 0; mt < 2; mt++) {
        int rr0 = row0 + wm * 32 + mt * 16 + g;
        int rr1 = rr0 + 8;
#pragma unroll
        for (int nt = 0; nt < 8; nt++) {
            int cc = col0 + wn * 64 + nt * 8 + 2 * t4;
            float s0 = 1.f / (1.f + __expf(-c[mt][nt][0]));
            float s1 = 1.f / (1.f + __expf(-c[mt][nt][1]));
            float s2 = 1.f / (1.f + __expf(-c[mt][nt][2]));
            float s3 = 1.f / (1.f + __expf(-c[mt][nt][3]));
            if (rr0 < n) {
                if (cc + 1 < n) *(float2*)(out + (size_t)rr0 * n + cc) = make_float2(s0, s1);
                else if (cc < n) out[(size_t)rr0 * n + cc] = s0;
            }
            if (rr1 < n) {
                if (cc + 1 < n) *(float2*)(out + (size_t)rr1 * n + cc) = make_float2(s2, s3);
                else if (cc < n) out[(size_t)rr1 * n + cc] = s2;
            }
        }
    }
}

// ---------------- final scalar ---------------------------------------------
__global__ void finalize_kernel(float* __restrict__ out, int E, long long loss_off,
                                int has_loss) {
    if (has_loss && threadIdx.x == 0 && blockIdx.x == 0) {
        out[loss_off] = (float)(g_loss[0] / (double)E + g_loss[1] / (double)E);
    }
}

// ---------------- launcher -------------------------------------------------
extern "C" void kernel_launch(void* const* d_in, const int* in_sizes, int n_in,
                              void* d_out, int out_size) {
    // inputs: 0=q, 1=x, 2=edge_index, 3=neg_edge_index,
    //         4=W_rel0, 5=W_root0, 6=b0, 7=W_rel1, 8=W_root1, 9=b1
    const float* x      = (const float*)d_in[1];
    const void*  ei     = d_in[2];
    const void*  nei    = d_in[3];
    const float* Wrel0  = (const float*)d_in[4];
    const float* Wroot0 = (const float*)d_in[5];
    const float* b0     = (const float*)d_in[6];
    const float* Wrel1  = (const float*)d_in[7];
    const float* Wroot1 = (const float*)d_in[8];
    const float* b1     = (const float*)d_in[9];

    int n = in_sizes[1] / DIN;      // 10000
    int E = in_sizes[2] / 2;        // 320000
    float* out = (float*)d_out;

    zero_kernel<<<(NN + 255) / 256, 256>>>();
    detect_kernel<<<1, 32>>>(ei, E, n);

    unsigned eb = (unsigned)((E + 255) / 256);
    count_kernel<<<eb, 256>>>(ei, E);
    scan_kernel<<<1, 1024>>>(n);
    fill_kernel<<<eb, 256>>>(ei, E);

    float* agg0 = nullptr; cudaGetSymbolAddress((void**)&agg0, g_agg0);
    float* agg1 = nullptr; cudaGetSymbolAddress((void**)&agg1, g_agg1);
    float* h0p  = nullptr; cudaGetSymbolAddress((void**)&h0p,  g_h0);

    gather_kernel<<<n, 128>>>(x, agg0);
    dense0_kernel<<<(n + 7) / 8, 128>>>(x, Wrel0, Wroot0, b0, n);
    gather_kernel<<<n, 128>>>(h0p, agg1);
    dense1_kernel<<<(n + 7) / 8, 64>>>(Wrel1, Wroot1, b1, n);
    loss_kernel<<<1024, 256>>>(ei, nei, E);

    cudaFuncSetAttribute(sim_mma_kernel,
                         cudaFuncAttributeMaxDynamicSharedMemorySize, 65536);
    dim3 grid((n + 127) / 128, (n + 127) / 128);
    sim_mma_kernel<<<grid, 256, 65536>>>(out, n);

    long long nn2 = (long long)n * n;
    int has_loss = ((long long)out_size > nn2) ? 1 : 0;
    finalize_kernel<<<1, 1>>>(out, E, nn2, has_loss);
}

// round 14
// speedup vs baseline: 1.5510x; 1.1487x over previous
#include <cuda_runtime.h>
#include <math.h>

#define NN    10000
#define DIN   128
#define DHID  128
#define DOUT  64
#define EMAX  524288

// ---------------- scratch (device globals; no allocation allowed) ----------
__device__ float  g_agg0[NN * DIN];
__device__ float  g_h0  [NN * DHID];
__device__ float  g_agg1[NN * DHID];
__device__ float  g_h1  [NN * DOUT];
__device__ float  g_hn  [NN * DOUT];
__device__ double g_loss[2];
__device__ int    g_is64;
__device__ int    g_deg [NN];
__device__ int    g_off [NN];
__device__ int    g_cur [NN];
__device__ int    g_srclist[EMAX];

// ---------------- zero scratch ---------------------------------------------
__global__ void zero_kernel() {
    int i = blockIdx.x * blockDim.x + threadIdx.x;
    if (i < NN) g_deg[i] = 0;
    if (i < 2)  g_loss[i] = 0.0;
}

// ---------------- detect edge-index dtype (int64 vs int32) -----------------
__global__ void detect_kernel(const void* __restrict__ ei, int E, int n) {
    if (blockIdx.x == 0 && threadIdx.x == 0) {
        const long long* p = (const long long*)ei;
        int m = E < 1024 ? E : 1024;
        int is64 = 1;
        for (int i = 0; i < m; i++) {
            long long v = p[i];
            if (v < 0 || v >= (long long)n) { is64 = 0; break; }
        }
        g_is64 = is64;
    }
}

__device__ __forceinline__ long long load_idx(const void* p, long long i, int is64) {
    return is64 ? ((const long long*)p)[i] : (long long)((const int*)p)[i];
}

// ---------------- CSR build: count, scan, fill -----------------------------
__global__ void count_kernel(const void* __restrict__ ei, int E) {
    int e = blockIdx.x * blockDim.x + threadIdx.x;
    if (e >= E) return;
    int is64 = g_is64;
    int d = (int)load_idx(ei, (long long)E + e, is64);
    atomicAdd(&g_deg[d], 1);
}

// two-level shfl scan: 1024 threads, each owns a contiguous chunk
__global__ void scan_kernel(int n) {
    __shared__ int wsum[32];
    int t = threadIdx.x;
    int lane = t & 31, w = t >> 5;
    int chunk = (n + 1023) >> 10;
    int start = t * chunk;
    int end = start + chunk; if (end > n) end = n;
    int local = 0;
    for (int i = start; i < end; i++) local += g_deg[i];
    int v = local;
#pragma unroll
    for (int o = 1; o < 32; o <<= 1) {
        int u = __shfl_up_sync(0xffffffffu, v, o);
        if (lane >= o) v += u;
    }
    if (lane == 31) wsum[w] = v;
    __syncthreads();
    if (w == 0) {
        int s = wsum[lane];
#pragma unroll
        for (int o = 1; o < 32; o <<= 1) {
            int u = __shfl_up_sync(0xffffffffu, s, o);
            if (lane >= o) s += u;
        }
        wsum[lane] = s;
    }
    __syncthreads();
    int running = (w > 0 ? wsum[w - 1] : 0) + (v - local);
    for (int i = start; i < end; i++) {
        g_off[i] = running;
        g_cur[i] = running;
        running += g_deg[i];
    }
}

__global__ void fill_kernel(const void* __restrict__ ei, int E) {
    int e = blockIdx.x * blockDim.x + threadIdx.x;
    if (e >= E) return;
    int is64 = g_is64;
    int s = (int)load_idx(ei, e, is64);
    int d = (int)load_idx(ei, (long long)E + e, is64);
    int pos = atomicAdd(&g_cur[d], 1);
    g_srclist[pos] = s;
}

// ---------------- gather aggregation: agg[n] = sum feat[src] ----------------
__global__ void gather_kernel(const float* __restrict__ feat,
                              float* __restrict__ outp) {
    int nidx = blockIdx.x;
    int t = threadIdx.x;  // 128
    int off = g_off[nidx];
    int deg = g_deg[nidx];
    float acc = 0.f;
    int i = 0;
    for (; i + 4 <= deg; i += 4) {
        int s0 = g_srclist[off + i + 0];
        int s1 = g_srclist[off + i + 1];
        int s2 = g_srclist[off + i + 2];
        int s3 = g_srclist[off + i + 3];
        float v0 = feat[(size_t)s0 * 128 + t];
        float v1 = feat[(size_t)s1 * 128 + t];
        float v2 = feat[(size_t)s2 * 128 + t];
        float v3 = feat[(size_t)s3 * 128 + t];
        acc += (v0 + v1) + (v2 + v3);
    }
    for (; i < deg; i++) {
        int s = g_srclist[off + i];
        acc += feat[(size_t)s * 128 + t];
    }
    outp[(size_t)nidx * 128 + t] = acc;
}

// ---------------- dense layer 0: 8 rows/block, h0 = tanh(...) --------------
__global__ void __launch_bounds__(128) dense0_kernel(
        const float* __restrict__ x, const float* __restrict__ Wrel,
        const float* __restrict__ Wroot, const float* __restrict__ b, int n) {
    int rowb = blockIdx.x * 8;
    int t = threadIdx.x;  // 128
    __shared__ float xs[8][128];
    __shared__ float as[8][128];
#pragma unroll
    for (int r = 0; r < 8; r++) {
        int rr = rowb + r;
        float xv = 0.f, av = 0.f;
        if (rr < n) {
            xv = x[(size_t)rr * DIN + t];
            av = g_agg0[(size_t)rr * DIN + t];
        }
        xs[r][t] = xv;
        as[r][t] = av;
    }
    __syncthreads();
    float acc[8];
    float bb = b[t];
#pragma unroll
    for (int r = 0; r < 8; r++) acc[r] = bb;
#pragma unroll 4
    for (int k = 0; k < DIN; k++) {
        float wr = Wroot[k * DHID + t];
        float wl = Wrel [k * DHID + t];
#pragma unroll
        for (int r = 0; r < 8; r++) {
            acc[r] = fmaf(xs[r][k], wr, acc[r]);
            acc[r] = fmaf(as[r][k], wl, acc[r]);
        }
    }
#pragma unroll
    for (int r = 0; r < 8; r++) {
        int rr = rowb + r;
        if (rr < n) g_h0[(size_t)rr * DHID + t] = tanhf(acc[r]);
    }
}

// ---------------- dense layer 1 + row normalization (8 rows/block) ---------
__global__ void __launch_bounds__(64) dense1_kernel(
        const float* __restrict__ Wrel, const float* __restrict__ Wroot,
        const float* __restrict__ b, int n) {
    int rowb = blockIdx.x * 8;
    int t = threadIdx.x;  // 64
    __shared__ float hs[8][128];
    __shared__ float as[8][128];
    __shared__ float wsum[8][2];
#pragma unroll
    for (int r = 0; r < 8; r++) {
        int rr = rowb + r;
        float h0v = 0.f, h1v = 0.f, a0v = 0.f, a1v = 0.f;
        if (rr < n) {
            h0v = g_h0  [(size_t)rr * DHID + t];
            h1v = g_h0  [(size_t)rr * DHID + t + 64];
            a0v = g_agg1[(size_t)rr * DHID + t];
            a1v = g_agg1[(size_t)rr * DHID + t + 64];
        }
        hs[r][t] = h0v; hs[r][t + 64] = h1v;
        as[r][t] = a0v; as[r][t + 64] = a1v;
    }
    __syncthreads();
    float acc[8];
    float bb = b[t];
#pragma unroll
    for (int r = 0; r < 8; r++) acc[r] = bb;
#pragma unroll 4
    for (int k = 0; k < DHID; k++) {
        float wr = Wroot[k * DOUT + t];
        float wl = Wrel [k * DOUT + t];
#pragma unroll
        for (int r = 0; r < 8; r++) {
            acc[r] = fmaf(hs[r][k], wr, acc[r]);
            acc[r] = fmaf(as[r][k], wl, acc[r]);
        }
    }
    int lane = t & 31, wid = t >> 5;
#pragma unroll
    for (int r = 0; r < 8; r++) {
        float sq = acc[r] * acc[r];
#pragma unroll
        for (int off = 16; off; off >>= 1) sq += __shfl_xor_sync(0xffffffffu, sq, off);
        if (lane == 0) wsum[r][wid] = sq;
    }
    __syncthreads();
#pragma unroll
    for (int r = 0; r < 8; r++) {
        int rr = rowb + r;
        if (rr >= n) continue;
        float nrm = sqrtf(wsum[r][0] + wsum[r][1]);
        g_h1[(size_t)rr * DOUT + t] = acc[r];
        g_hn[(size_t)rr * DOUT + t] = acc[r] / fmaxf(nrm, 1e-8f);
    }
}

// ---------------- reconstruction loss (warp per edge, double accum) --------
__global__ void loss_kernel(const void* __restrict__ ei,
                            const void* __restrict__ nei, int E) {
    __shared__ double sh[2];
    if (threadIdx.x < 2) sh[threadIdx.x] = 0.0;
    __syncthreads();
    int is64 = g_is64;
    int wglobal = (blockIdx.x * blockDim.x + threadIdx.x) >> 5;
    int lane = threadIdx.x & 31;
    int nwarps = (gridDim.x * blockDim.x) >> 5;
    double pos = 0.0, neg = 0.0;
    for (int task = wglobal; task < 2 * E; task += nwarps) {
        int is_neg = task >= E;
        int e = is_neg ? task - E : task;
        const void* idx = is_neg ? nei : ei;
        long long s = load_idx(idx, e, is64);
        long long d = load_idx(idx, (long long)E + e, is64);
        const float* a = g_h1 + s * DOUT;
        const float* bp = g_h1 + d * DOUT;
        float p = a[lane] * bp[lane] + a[lane + 32] * bp[lane + 32];
#pragma unroll
        for (int off = 16; off; off >>= 1) p += __shfl_xor_sync(0xffffffffu, p, off);
        if (lane == 0) {
            float z = is_neg ? p : -p;   // softplus argument
            float sp = fmaxf(z, 0.f) + log1pf(expf(-fabsf(z)));
            if (is_neg) neg += (double)sp; else pos += (double)sp;
        }
    }
    if (lane == 0) {
        atomicAdd(&sh[0], pos);
        atomicAdd(&sh[1], neg);
    }
    __syncthreads();
    if (threadIdx.x == 0) {
        atomicAdd(&g_loss[0], sh[0]);
        atomicAdd(&g_loss[1], sh[1]);
    }
}

// ---------------- sim matrix via tf32 mma.sync, triangular grid -------------
__device__ __forceinline__ unsigned f2tf32(float f) {
    unsigned u;
    asm("cvt.rna.tf32.f32 %0, %1;" : "=r"(u) : "f"(f));
    return u;
}

// Upper-triangle tiles only (bi <= bj). Off-diagonal tiles store normal from
// registers AND the mirrored tile via 129-padded smem staging (conflict-free
// transposed read, coalesced global write). Values are identical either way.
__global__ void __launch_bounds__(256) sim_mma_kernel(float* __restrict__ out,
                                                      int n, int T) {
    extern __shared__ unsigned sm[];
    unsigned* As = sm;               // 128*64 words
    unsigned* Bs = sm + 128 * 64;    // 128*64 words
    int tid = threadIdx.x;

    // decode linear upper-triangle index -> (bi, bj), bi <= bj
    int p = blockIdx.x;
    int bi = (int)((2.f * T + 1.f - sqrtf((2.f * T + 1.f) * (2.f * T + 1.f) - 8.f * p)) * 0.5f);
    while (bi > 0 && bi * T - (bi * (bi - 1)) / 2 > p) bi--;
    while ((bi + 1) * T - ((bi + 1) * bi) / 2 <= p) bi++;
    int bj = bi + (p - (bi * T - (bi * (bi - 1)) / 2));

    int row0 = bi * 128, col0 = bj * 128;

#pragma unroll
    for (int l = 0; l < 8; l++) {
        int f = tid + l * 256;        // 0..2047
        int r = f >> 4;               // 0..127
        int kc = (f & 15) * 4;        // 0..60
        int ra = row0 + r, rb = col0 + r;
        float4 va = make_float4(0.f, 0.f, 0.f, 0.f);
        float4 vb = make_float4(0.f, 0.f, 0.f, 0.f);
        if (ra < n) va = *(const float4*)(g_hn + (size_t)ra * DOUT + kc);
        if (rb < n) vb = *(const float4*)(g_hn + (size_t)rb * DOUT + kc);
        int sc = kc ^ ((r & 7) << 2);
        uint4 ua = make_uint4(f2tf32(va.x), f2tf32(va.y), f2tf32(va.z), f2tf32(va.w));
        uint4 ub = make_uint4(f2tf32(vb.x), f2tf32(vb.y), f2tf32(vb.z), f2tf32(vb.w));
        *(uint4*)(As + r * 64 + sc) = ua;
        *(uint4*)(Bs + r * 64 + sc) = ub;
    }
    __syncthreads();

    int w = tid >> 5, lane = tid & 31;
    int wm = w & 3, wn = w >> 2;      // warp at rows wm*32, cols wn*64
    int g = lane >> 2, t4 = lane & 3;

    float c[2][8][4];
#pragma unroll
    for (int mt = 0; mt < 2; mt++)
#pragma unroll
        for (int nt = 0; nt < 8; nt++)
#pragma unroll
            for (int q = 0; q < 4; q++) c[mt][nt][q] = 0.f;

#pragma unroll
    for (int ks = 0; ks < 8; ks++) {
        int k0 = ks * 8;
        unsigned a[2][4];
#pragma unroll
        for (int mt = 0; mt < 2; mt++) {
            int r0 = wm * 32 + mt * 16 + g;
            int r1 = r0 + 8;
            int sw0 = (r0 & 7) << 2;
            int sw1 = (r1 & 7) << 2;
            a[mt][0] = As[r0 * 64 + ((k0 + t4) ^ sw0)];
            a[mt][1] = As[r1 * 64 + ((k0 + t4) ^ sw1)];
            a[mt][2] = As[r0 * 64 + ((k0 + t4 + 4) ^ sw0)];
            a[mt][3] = As[r1 * 64 + ((k0 + t4 + 4) ^ sw1)];
        }
#pragma unroll
        for (int nt = 0; nt < 8; nt++) {
            int cb = wn * 64 + nt * 8 + g;
            int swb = (cb & 7) << 2;
            unsigned b0 = Bs[cb * 64 + ((k0 + t4) ^ swb)];
            unsigned b1 = Bs[cb * 64 + ((k0 + t4 + 4) ^ swb)];
#pragma unroll
            for (int mt = 0; mt < 2; mt++) {
                asm volatile(
                    "mma.sync.aligned.m16n8k8.row.col.f32.tf32.tf32.f32 "
                    "{%0,%1,%2,%3}, {%4,%5,%6,%7}, {%8,%9}, {%0,%1,%2,%3};"
                    : "+f"(c[mt][nt][0]), "+f"(c[mt][nt][1]),
                      "+f"(c[mt][nt][2]), "+f"(c[mt][nt][3])
                    : "r"(a[mt][0]), "r"(a[mt][1]), "r"(a[mt][2]), "r"(a[mt][3]),
                      "r"(b0), "r"(b1));
            }
        }
    }

    int mirror = (bi != bj);
    float* S = (float*)sm;           // reuse As/Bs as 128x129-padded staging
    if (mirror) __syncthreads();     // all warps done reading As/Bs

    // epilogue: sigmoid + normal store (+ staging for mirror)
#pragma unroll
    for (int mt = 0; mt < 2; mt++) {
        int rl0 = wm * 32 + mt * 16 + g;
        int rl1 = rl0 + 8;
        int rr0 = row0 + rl0;
        int rr1 = row0 + rl1;
#pragma unroll
        for (int nt = 0; nt < 8; nt++) {
            int cl = wn * 64 + nt * 8 + 2 * t4;
            int cc = col0 + cl;
            float s0 = 1.f / (1.f + __expf(-c[mt][nt][0]));
            float s1 = 1.f / (1.f + __expf(-c[mt][nt][1]));
            float s2 = 1.f / (1.f + __expf(-c[mt][nt][2]));
            float s3 = 1.f / (1.f + __expf(-c[mt][nt][3]));
            if (rr0 < n) {
                if (cc + 1 < n) *(float2*)(out + (size_t)rr0 * n + cc) = make_float2(s0, s1);
                else if (cc < n) out[(size_t)rr0 * n + cc] = s0;
            }
            if (rr1 < n) {
                if (cc + 1 < n) *(float2*)(out + (size_t)rr1 * n + cc) = make_float2(s2, s3);
                else if (cc < n) out[(size_t)rr1 * n + cc] = s2;
            }
            if (mirror) {
                S[rl0 * 129 + cl]     = s0;
                S[rl0 * 129 + cl + 1] = s1;
                S[rl1 * 129 + cl]     = s2;
                S[rl1 * 129 + cl + 1] = s3;
            }
        }
    }

    if (mirror) {
        __syncthreads();
        // mirrored tile: row (col0+cl), cols row0..row0+127; coalesced writes
        for (int cl = w; cl < 128; cl += 8) {
            int gr = col0 + cl;
            if (gr >= n) continue;
            size_t base = (size_t)gr * n + row0;
#pragma unroll
            for (int j = 0; j < 4; j++) {
                int k = lane + j * 32;
                if (row0 + k < n) out[base + k] = S[k * 129 + cl];
            }
        }
    }
}

// ---------------- final scalar ---------------------------------------------
__global__ void finalize_kernel(float* __restrict__ out, int E, long long loss_off,
                                int has_loss) {
    if (has_loss && threadIdx.x == 0 && blockIdx.x == 0) {
        out[loss_off] = (float)(g_loss[0] / (double)E + g_loss[1] / (double)E);
    }
}

// ---------------- launcher -------------------------------------------------
extern "C" void kernel_launch(void* const* d_in, const int* in_sizes, int n_in,
                              void* d_out, int out_size) {
    // inputs: 0=q, 1=x, 2=edge_index, 3=neg_edge_index,
    //         4=W_rel0, 5=W_root0, 6=b0, 7=W_rel1, 8=W_root1, 9=b1
    const float* x      = (const float*)d_in[1];
    const void*  ei     = d_in[2];
    const void*  nei    = d_in[3];
    const float* Wrel0  = (const float*)d_in[4];
    const float* Wroot0 = (const float*)d_in[5];
    const float* b0     = (const float*)d_in[6];
    const float* Wrel1  = (const float*)d_in[7];
    const float* Wroot1 = (const float*)d_in[8];
    const float* b1     = (const float*)d_in[9];

    int n = in_sizes[1] / DIN;      // 10000
    int E = in_sizes[2] / 2;        // 320000
    float* out = (float*)d_out;

    zero_kernel<<<(NN + 255) / 256, 256>>>();
    detect_kernel<<<1, 32>>>(ei, E, n);

    unsigned eb = (unsigned)((E + 255) / 256);
    count_kernel<<<eb, 256>>>(ei, E);
    scan_kernel<<<1, 1024>>>(n);
    fill_kernel<<<eb, 256>>>(ei, E);

    float* agg0 = nullptr; cudaGetSymbolAddress((void**)&agg0, g_agg0);
    float* agg1 = nullptr; cudaGetSymbolAddress((void**)&agg1, g_agg1);
    float* h0p  = nullptr; cudaGetSymbolAddress((void**)&h0p,  g_h0);

    gather_kernel<<<n, 128>>>(x, agg0);
    dense0_kernel<<<(n + 7) / 8, 128>>>(x, Wrel0, Wroot0, b0, n);
    gather_kernel<<<n, 128>>>(h0p, agg1);
    dense1_kernel<<<(n + 7) / 8, 64>>>(Wrel1, Wroot1, b1, n);
    loss_kernel<<<1024, 256>>>(ei, nei, E);

    int T = (n + 127) / 128;
    int L = T * (T + 1) / 2;
    int smem_bytes = 128 * 129 * 4;   // 66048 >= 2*128*64*4
    cudaFuncSetAttribute(sim_mma_kernel,
                         cudaFuncAttributeMaxDynamicSharedMemorySize, smem_bytes);
    sim_mma_kernel<<<L, 256, smem_bytes>>>(out, n, T);

    long long nn2 = (long long)n * n;
    int has_loss = ((long long)out_size > nn2) ? 1 : 0;
    finalize_kernel<<<1, 1>>>(out, E, nn2, has_loss);
}

// round 16
// speedup vs baseline: 1.5775x; 1.0171x over previous
#include <cuda_runtime.h>
#include <math.h>

#define NN    10000
#define DIN   128
#define DHID  128
#define DOUT  64
#define EMAX  524288
#define SCANB 40   // ceil(10000/256)

// ---------------- scratch (device globals; no allocation allowed) ----------
__device__ float  g_agg0[NN * DIN];
__device__ float  g_h0  [NN * DHID];
__device__ float  g_agg1[NN * DHID];
__device__ float  g_h1  [NN * DOUT];
__device__ float  g_hn  [NN * DOUT];
__device__ double g_loss[2];
__device__ int    g_is64;
__device__ int    g_deg [NN];
__device__ int    g_off [NN];
__device__ int    g_cur [NN];
__device__ int    g_srclist[EMAX];
__device__ int    g_bsum[SCANB];
__device__ int    g_bbase[SCANB];

// ---------------- zero scratch ---------------------------------------------
__global__ void zero_kernel() {
    int i = blockIdx.x * blockDim.x + threadIdx.x;
    if (i < NN) g_deg[i] = 0;
    if (i < 2)  g_loss[i] = 0.0;
    if (i == 2) g_is64 = 1;
}

// ---------------- detect edge-index dtype (parallel, 1 block) --------------
__global__ void detect_kernel(const void* __restrict__ ei, int E, int n) {
    int t = threadIdx.x;           // 1024 threads
    int m = E < 1024 ? E : 1024;
    int bad = 0;
    if (t < m) {
        long long v = ((const long long*)ei)[t];
        bad = (v < 0 || v >= (long long)n);
    }
    if (__syncthreads_or(bad)) {
        if (t == 0) g_is64 = 0;
    }
}

__device__ __forceinline__ long long load_idx(const void* p, long long i, int is64) {
    return is64 ? ((const long long*)p)[i] : (long long)((const int*)p)[i];
}

// ---------------- CSR build: count, 3-phase scan, fill ---------------------
__global__ void count_kernel(const void* __restrict__ ei, int E) {
    int e = blockIdx.x * blockDim.x + threadIdx.x;
    if (e >= E) return;
    int is64 = g_is64;
    int d = (int)load_idx(ei, (long long)E + e, is64);
    atomicAdd(&g_deg[d], 1);
}

// phase 1: per-block sums (SCANB blocks x 256)
__global__ void scan1_kernel(int n) {
    __shared__ int ws[8];
    int t = threadIdx.x;
    int i = blockIdx.x * 256 + t;
    int v = (i < n) ? g_deg[i] : 0;
    int lane = t & 31, w = t >> 5;
    int s = v;
#pragma unroll
    for (int o = 16; o; o >>= 1) s += __shfl_xor_sync(0xffffffffu, s, o);
    if (lane == 0) ws[w] = s;
    __syncthreads();
    if (t == 0) {
        int tot = 0;
#pragma unroll
        for (int k = 0; k < 8; k++) tot += ws[k];
        g_bsum[blockIdx.x] = tot;
    }
}

// phase 2: exclusive scan of SCANB partials (1 block, 64 threads)
__global__ void scan2_kernel() {
    int t = threadIdx.x;
    int v = (t < SCANB) ? g_bsum[t] : 0;
    __shared__ int sh[64];
    sh[t] = v;
    __syncthreads();
    if (t == 0) {
        int run = 0;
        for (int k = 0; k < SCANB; k++) { int x = sh[k]; sh[k] = run; run += x; }
    }
    __syncthreads();
    if (t < SCANB) g_bbase[t] = sh[t];
}

// phase 3: block-local exclusive scan + base -> offsets
__global__ void scan3_kernel(int n) {
    __shared__ int ws[8];
    int t = threadIdx.x;
    int i = blockIdx.x * 256 + t;
    int v = (i < n) ? g_deg[i] : 0;
    int lane = t & 31, w = t >> 5;
    int s = v;
#pragma unroll
    for (int o = 1; o < 32; o <<= 1) {
        int u = __shfl_up_sync(0xffffffffu, s, o);
        if (lane >= o) s += u;
    }
    if (lane == 31) ws[w] = s;
    __syncthreads();
    if (w == 0 && lane < 8) {
        int x = ws[lane];
#pragma unroll
        for (int o = 1; o < 8; o <<= 1) {
            int u = __shfl_up_sync(0xffu, x, o, 8);
            if (lane >= o) x += u;
        }
        ws[lane] = x;
    }
    __syncthreads();
    int excl = (w > 0 ? ws[w - 1] : 0) + (s - v) + g_bbase[blockIdx.x];
    if (i < n) {
        g_off[i] = excl;
        g_cur[i] = excl;
    }
}

__global__ void fill_kernel(const void* __restrict__ ei, int E) {
    int e = blockIdx.x * blockDim.x + threadIdx.x;
    if (e >= E) return;
    int is64 = g_is64;
    int s = (int)load_idx(ei, e, is64);
    int d = (int)load_idx(ei, (long long)E + e, is64);
    int pos = atomicAdd(&g_cur[d], 1);
    g_srclist[pos] = s;
}

// ---------------- gather aggregation: agg[n] = sum feat[src] ----------------
__global__ void gather_kernel(const float* __restrict__ feat,
                              float* __restrict__ outp) {
    int nidx = blockIdx.x;
    int t = threadIdx.x;  // 128
    int off = g_off[nidx];
    int deg = g_deg[nidx];
    float acc = 0.f;
    int i = 0;
    for (; i + 4 <= deg; i += 4) {
        int s0 = g_srclist[off + i + 0];
        int s1 = g_srclist[off + i + 1];
        int s2 = g_srclist[off + i + 2];
        int s3 = g_srclist[off + i + 3];
        float v0 = feat[(size_t)s0 * 128 + t];
        float v1 = feat[(size_t)s1 * 128 + t];
        float v2 = feat[(size_t)s2 * 128 + t];
        float v3 = feat[(size_t)s3 * 128 + t];
        acc += (v0 + v1) + (v2 + v3);
    }
    for (; i < deg; i++) {
        int s = g_srclist[off + i];
        acc += feat[(size_t)s * 128 + t];
    }
    outp[(size_t)nidx * 128 + t] = acc;
}

// ---------------- dense layer 0: 8 rows/block, h0 = tanh(...) --------------
__global__ void __launch_bounds__(128) dense0_kernel(
        const float* __restrict__ x, const float* __restrict__ Wrel,
        const float* __restrict__ Wroot, const float* __restrict__ b, int n) {
    int rowb = blockIdx.x * 8;
    int t = threadIdx.x;  // 128
    __shared__ float xs[8][128];
    __shared__ float as[8][128];
#pragma unroll
    for (int r = 0; r < 8; r++) {
        int rr = rowb + r;
        float xv = 0.f, av = 0.f;
        if (rr < n) {
            xv = x[(size_t)rr * DIN + t];
            av = g_agg0[(size_t)rr * DIN + t];
        }
        xs[r][t] = xv;
        as[r][t] = av;
    }
    __syncthreads();
    float acc[8];
    float bb = b[t];
#pragma unroll
    for (int r = 0; r < 8; r++) acc[r] = bb;
#pragma unroll 4
    for (int k = 0; k < DIN; k++) {
        float wr = Wroot[k * DHID + t];
        float wl = Wrel [k * DHID + t];
#pragma unroll
        for (int r = 0; r < 8; r++) {
            acc[r] = fmaf(xs[r][k], wr, acc[r]);
            acc[r] = fmaf(as[r][k], wl, acc[r]);
        }
    }
#pragma unroll
    for (int r = 0; r < 8; r++) {
        int rr = rowb + r;
        if (rr < n) g_h0[(size_t)rr * DHID + t] = tanhf(acc[r]);
    }
}

// ---------------- dense layer 1 + row normalization (8 rows/block) ---------
__global__ void __launch_bounds__(64) dense1_kernel(
        const float* __restrict__ Wrel, const float* __restrict__ Wroot,
        const float* __restrict__ b, int n) {
    int rowb = blockIdx.x * 8;
    int t = threadIdx.x;  // 64
    __shared__ float hs[8][128];
    __shared__ float as[8][128];
    __shared__ float wsum[8][2];
#pragma unroll
    for (int r = 0; r < 8; r++) {
        int rr = rowb + r;
        float h0v = 0.f, h1v = 0.f, a0v = 0.f, a1v = 0.f;
        if (rr < n) {
            h0v = g_h0  [(size_t)rr * DHID + t];
            h1v = g_h0  [(size_t)rr * DHID + t + 64];
            a0v = g_agg1[(size_t)rr * DHID + t];
            a1v = g_agg1[(size_t)rr * DHID + t + 64];
        }
        hs[r][t] = h0v; hs[r][t + 64] = h1v;
        as[r][t] = a0v; as[r][t + 64] = a1v;
    }
    __syncthreads();
    float acc[8];
    float bb = b[t];
#pragma unroll
    for (int r = 0; r < 8; r++) acc[r] = bb;
#pragma unroll 4
    for (int k = 0; k < DHID; k++) {
        float wr = Wroot[k * DOUT + t];
        float wl = Wrel [k * DOUT + t];
#pragma unroll
        for (int r = 0; r < 8; r++) {
            acc[r] = fmaf(hs[r][k], wr, acc[r]);
            acc[r] = fmaf(as[r][k], wl, acc[r]);
        }
    }
    int lane = t & 31, wid = t >> 5;
#pragma unroll
    for (int r = 0; r < 8; r++) {
        float sq = acc[r] * acc[r];
#pragma unroll
        for (int off = 16; off; off >>= 1) sq += __shfl_xor_sync(0xffffffffu, sq, off);
        if (lane == 0) wsum[r][wid] = sq;
    }
    __syncthreads();
#pragma unroll
    for (int r = 0; r < 8; r++) {
        int rr = rowb + r;
        if (rr >= n) continue;
        float nrm = sqrtf(wsum[r][0] + wsum[r][1]);
        g_h1[(size_t)rr * DOUT + t] = acc[r];
        g_hn[(size_t)rr * DOUT + t] = acc[r] / fmaxf(nrm, 1e-8f);
    }
}

// ---------------- reconstruction loss (warp per edge, double accum) --------
__global__ void loss_kernel(const void* __restrict__ ei,
                            const void* __restrict__ nei, int E) {
    __shared__ double sh[2];
    if (threadIdx.x < 2) sh[threadIdx.x] = 0.0;
    __syncthreads();
    int is64 = g_is64;
    int wglobal = (blockIdx.x * blockDim.x + threadIdx.x) >> 5;
    int lane = threadIdx.x & 31;
    int nwarps = (gridDim.x * blockDim.x) >> 5;
    double pos = 0.0, neg = 0.0;
    for (int task = wglobal; task < 2 * E; task += nwarps) {
        int is_neg = task >= E;
        int e = is_neg ? task - E : task;
        const void* idx = is_neg ? nei : ei;
        long long s = load_idx(idx, e, is64);
        long long d = load_idx(idx, (long long)E + e, is64);
        const float* a = g_h1 + s * DOUT;
        const float* bp = g_h1 + d * DOUT;
        float p = a[lane] * bp[lane] + a[lane + 32] * bp[lane + 32];
#pragma unroll
        for (int off = 16; off; off >>= 1) p += __shfl_xor_sync(0xffffffffu, p, off);
        if (lane == 0) {
            float z = is_neg ? p : -p;   // softplus argument
            float sp = fmaxf(z, 0.f) + log1pf(expf(-fabsf(z)));
            if (is_neg) neg += (double)sp; else pos += (double)sp;
        }
    }
    if (lane == 0) {
        atomicAdd(&sh[0], pos);
        atomicAdd(&sh[1], neg);
    }
    __syncthreads();
    if (threadIdx.x == 0) {
        atomicAdd(&g_loss[0], sh[0]);
        atomicAdd(&g_loss[1], sh[1]);
    }
}

// ---------------- sim matrix via tf32 mma.sync, triangular grid -------------
__device__ __forceinline__ unsigned f2tf32(float f) {
    unsigned u;
    asm("cvt.rna.tf32.f32 %0, %1;" : "=r"(u) : "f"(f));
    return u;
}

// Upper-triangle tiles only (bi <= bj). Off-diagonal tiles store normal from
// registers AND the mirrored tile via 129-padded smem staging (conflict-free
// transposed read, coalesced global write). Values are identical either way.
__global__ void __launch_bounds__(256) sim_mma_kernel(float* __restrict__ out,
                                                      int n, int T) {
    extern __shared__ unsigned sm[];
    unsigned* As = sm;               // 128*64 words
    unsigned* Bs = sm + 128 * 64;    // 128*64 words
    int tid = threadIdx.x;

    // decode linear upper-triangle index -> (bi, bj), bi <= bj
    int p = blockIdx.x;
    int bi = (int)((2.f * T + 1.f - sqrtf((2.f * T + 1.f) * (2.f * T + 1.f) - 8.f * p)) * 0.5f);
    while (bi > 0 && bi * T - (bi * (bi - 1)) / 2 > p) bi--;
    while ((bi + 1) * T - ((bi + 1) * bi) / 2 <= p) bi++;
    int bj = bi + (p - (bi * T - (bi * (bi - 1)) / 2));

    int row0 = bi * 128, col0 = bj * 128;

#pragma unroll
    for (int l = 0; l < 8; l++) {
        int f = tid + l * 256;        // 0..2047
        int r = f >> 4;               // 0..127
        int kc = (f & 15) * 4;        // 0..60
        int ra = row0 + r, rb = col0 + r;
        float4 va = make_float4(0.f, 0.f, 0.f, 0.f);
        float4 vb = make_float4(0.f, 0.f, 0.f, 0.f);
        if (ra < n) va = *(const float4*)(g_hn + (size_t)ra * DOUT + kc);
        if (rb < n) vb = *(const float4*)(g_hn + (size_t)rb * DOUT + kc);
        int sc = kc ^ ((r & 7) << 2);
        uint4 ua = make_uint4(f2tf32(va.x), f2tf32(va.y), f2tf32(va.z), f2tf32(va.w));
        uint4 ub = make_uint4(f2tf32(vb.x), f2tf32(vb.y), f2tf32(vb.z), f2tf32(vb.w));
        *(uint4*)(As + r * 64 + sc) = ua;
        *(uint4*)(Bs + r * 64 + sc) = ub;
    }
    __syncthreads();

    int w = tid >> 5, lane = tid & 31;
    int wm = w & 3, wn = w >> 2;      // warp at rows wm*32, cols wn*64
    int g = lane >> 2, t4 = lane & 3;

    float c[2][8][4];
#pragma unroll
    for (int mt = 0; mt < 2; mt++)
#pragma unroll
        for (int nt = 0; nt < 8; nt++)
#pragma unroll
            for (int q = 0; q < 4; q++) c[mt][nt][q] = 0.f;

#pragma unroll
    for (int ks = 0; ks < 8; ks++) {
        int k0 = ks * 8;
        unsigned a[2][4];
#pragma unroll
        for (int mt = 0; mt < 2; mt++) {
            int r0 = wm * 32 + mt * 16 + g;
            int r1 = r0 + 8;
            int sw0 = (r0 & 7) << 2;
            int sw1 = (r1 & 7) << 2;
            a[mt][0] = As[r0 * 64 + ((k0 + t4) ^ sw0)];
            a[mt][1] = As[r1 * 64 + ((k0 + t4) ^ sw1)];
            a[mt][2] = As[r0 * 64 + ((k0 + t4 + 4) ^ sw0)];
            a[mt][3] = As[r1 * 64 + ((k0 + t4 + 4) ^ sw1)];
        }
#pragma unroll
        for (int nt = 0; nt < 8; nt++) {
            int cb = wn * 64 + nt * 8 + g;
            int swb = (cb & 7) << 2;
            unsigned b0 = Bs[cb * 64 + ((k0 + t4) ^ swb)];
            unsigned b1 = Bs[cb * 64 + ((k0 + t4 + 4) ^ swb)];
#pragma unroll
            for (int mt = 0; mt < 2; mt++) {
                asm volatile(
                    "mma.sync.aligned.m16n8k8.row.col.f32.tf32.tf32.f32 "
                    "{%0,%1,%2,%3}, {%4,%5,%6,%7}, {%8,%9}, {%0,%1,%2,%3};"
                    : "+f"(c[mt][nt][0]), "+f"(c[mt][nt][1]),
                      "+f"(c[mt][nt][2]), "+f"(c[mt][nt][3])
                    : "r"(a[mt][0]), "r"(a[mt][1]), "r"(a[mt][2]), "r"(a[mt][3]),
                      "r"(b0), "r"(b1));
            }
        }
    }

    int mirror = (bi != bj);
    float* S = (float*)sm;           // reuse As/Bs as 128x129-padded staging
    if (mirror) __syncthreads();     // all warps done reading As/Bs

    // epilogue: sigmoid + normal store (+ staging for mirror)
#pragma unroll
    for (int mt = 0; mt < 2; mt++) {
        int rl0 = wm * 32 + mt * 16 + g;
        int rl1 = rl0 + 8;
        int rr0 = row0 + rl0;
        int rr1 = row0 + rl1;
#pragma unroll
        for (int nt = 0; nt < 8; nt++) {
            int cl = wn * 64 + nt * 8 + 2 * t4;
            int cc = col0 + cl;
            float s0 = 1.f / (1.f + __expf(-c[mt][nt][0]));
            float s1 = 1.f / (1.f + __expf(-c[mt][nt][1]));
            float s2 = 1.f / (1.f + __expf(-c[mt][nt][2]));
            float s3 = 1.f / (1.f + __expf(-c[mt][nt][3]));
            if (rr0 < n) {
                if (cc + 1 < n) *(float2*)(out + (size_t)rr0 * n + cc) = make_float2(s0, s1);
                else if (cc < n) out[(size_t)rr0 * n + cc] = s0;
            }
            if (rr1 < n) {
                if (cc + 1 < n) *(float2*)(out + (size_t)rr1 * n + cc) = make_float2(s2, s3);
                else if (cc < n) out[(size_t)rr1 * n + cc] = s2;
            }
            if (mirror) {
                S[rl0 * 129 + cl]     = s0;
                S[rl0 * 129 + cl + 1] = s1;
                S[rl1 * 129 + cl]     = s2;
                S[rl1 * 129 + cl + 1] = s3;
            }
        }
    }

    if (mirror) {
        __syncthreads();
        // mirrored tile: row (col0+cl), cols row0..row0+127; coalesced writes
        for (int cl = w; cl < 128; cl += 8) {
            int gr = col0 + cl;
            if (gr >= n) continue;
            size_t base = (size_t)gr * n + row0;
#pragma unroll
            for (int j = 0; j < 4; j++) {
                int k = lane + j * 32;
                if (row0 + k < n) out[base + k] = S[k * 129 + cl];
            }
        }
    }
}

// ---------------- final scalar ---------------------------------------------
__global__ void finalize_kernel(float* __restrict__ out, int E, long long loss_off,
                                int has_loss) {
    if (has_loss && threadIdx.x == 0 && blockIdx.x == 0) {
        out[loss_off] = (float)(g_loss[0] / (double)E + g_loss[1] / (double)E);
    }
}

// ---------------- launcher -------------------------------------------------
extern "C" void kernel_launch(void* const* d_in, const int* in_sizes, int n_in,
                              void* d_out, int out_size) {
    // inputs: 0=q, 1=x, 2=edge_index, 3=neg_edge_index,
    //         4=W_rel0, 5=W_root0, 6=b0, 7=W_rel1, 8=W_root1, 9=b1
    const float* x      = (const float*)d_in[1];
    const void*  ei     = d_in[2];
    const void*  nei    = d_in[3];
    const float* Wrel0  = (const float*)d_in[4];
    const float* Wroot0 = (const float*)d_in[5];
    const float* b0     = (const float*)d_in[6];
    const float* Wrel1  = (const float*)d_in[7];
    const float* Wroot1 = (const float*)d_in[8];
    const float* b1     = (const float*)d_in[9];

    int n = in_sizes[1] / DIN;      // 10000
    int E = in_sizes[2] / 2;        // 320000
    float* out = (float*)d_out;

    zero_kernel<<<(NN + 255) / 256, 256>>>();
    detect_kernel<<<1, 1024>>>(ei, E, n);

    unsigned eb = (unsigned)((E + 255) / 256);
    count_kernel<<<eb, 256>>>(ei, E);
    scan1_kernel<<<SCANB, 256>>>(n);
    scan2_kernel<<<1, 64>>>();
    scan3_kernel<<<SCANB, 256>>>(n);
    fill_kernel<<<eb, 256>>>(ei, E);

    float* agg0 = nullptr; cudaGetSymbolAddress((void**)&agg0, g_agg0);
    float* agg1 = nullptr; cudaGetSymbolAddress((void**)&agg1, g_agg1);
    float* h0p  = nullptr; cudaGetSymbolAddress((void**)&h0p,  g_h0);

    gather_kernel<<<n, 128>>>(x, agg0);
    dense0_kernel<<<(n + 7) / 8, 128>>>(x, Wrel0, Wroot0, b0, n);
    gather_kernel<<<n, 128>>>(h0p, agg1);
    dense1_kernel<<<(n + 7) / 8, 64>>>(Wrel1, Wroot1, b1, n);
    loss_kernel<<<1024, 256>>>(ei, nei, E);

    int T = (n + 127) / 128;
    int L = T * (T + 1) / 2;
    int smem_bytes = 128 * 129 * 4;   // 66048 >= 2*128*64*4
    cudaFuncSetAttribute(sim_mma_kernel,
                         cudaFuncAttributeMaxDynamicSharedMemorySize, smem_bytes);
    sim_mma_kernel<<<L, 256, smem_bytes>>>(out, n, T);

    long long nn2 = (long long)n * n;
    int has_loss = ((long long)out_size > nn2) ? 1 : 0;
    finalize_kernel<<<1, 1>>>(out, E, nn2, has_loss);
}